// round 6
// baseline (speedup 1.0000x reference)
#include <cuda_runtime.h>

// CalibrationLayer R6: slope/intercept chord table — minimal eval path.
//
// Per-bucket float2 {slope, intercept} of the chord in ABSOLUTE x coords:
//   b = floor(fma(xv, invw, -glo*invw)) ;  y = fma(slope, xv, intercept)
// No frac, no unpack, one convert. Adjacent chords agree exactly at shared
// edges, so bucket-boundary rounding slop is ~1 ulp — eval rounding is free.
// K=14336 buckets over [max(lo,-3.45), min(hi,3.45)]; table 112KB + 57KB
// build scratch = 114.7KB/CTA -> 2 CTAs x 1024 thr/SM. Out-of-grid tail
// (5.6e-4 of mass) + exact end clamps via rare global-scan fixup branch.

#define THREADS 1024
#define CTAS_PER_SM 2
#define GRID    (148 * CTAS_PER_SM)
#define KBUCK   14336
// [0, KBUCK) float2 table; edges scratch (KBUCK+1 floats) above it
#define EDGE_OFF (KBUCK * 2)
#define SMEM_BYTES (KBUCK * 8 + (KBUCK + 1) * 4)
#define GRANGE  3.45f

extern __shared__ float smem[];

__device__ __forceinline__ float slow_eval(float xv, int start,
                                           const float* __restrict__ ri,
                                           const float* __restrict__ ro,
                                           int R) {
    int j = min(max(start, 1), R - 1);
    while (__ldg(ri + j) <= xv) ++j;       // exact upper_bound
    while (__ldg(ri + j - 1) > xv) --j;
    float x0 = __ldg(ri + j - 1), x1 = __ldg(ri + j);
    float y0 = __ldg(ro + j - 1), y1 = __ldg(ro + j);
    return y0 + (y1 - y0) * __fdividef(xv - x0, x1 - x0);
}

__global__ __launch_bounds__(THREADS, CTAS_PER_SM)
void calib_kernel(const float* __restrict__ x,
                  const float* __restrict__ ri,
                  const float* __restrict__ ro,
                  float* __restrict__ out,
                  int n, int R) {
    float2* __restrict__ tab  = (float2*)smem;          // KBUCK records
    float*  __restrict__ edge = smem + EDGE_OFF;        // KBUCK+1 edge values

    const float lo = __ldg(&ri[0]);
    const float hi = __ldg(&ri[R - 1]);
    float glo = fmaxf(lo, -GRANGE);
    float ghi = fminf(hi,  GRANGE);
    if (!(ghi - glo > 1e-6f)) { glo = lo; ghi = hi; }
    const float w    = (ghi - glo) / (float)KBUCK;
    const float invw = (float)KBUCK / (ghi - glo);
    const float nglo = -glo * invw;        // fb = fma(xv, invw, nglo)

    // ---- pass 1: exact interpolant values at the K+1 grid edges ----
    // Edge e lies in exactly one interval: s0/s1 use identical fp expressions,
    // so the scatter ranges tile [0, K] exactly.
    for (int t = threadIdx.x; t < R - 1; t += THREADS) {
        const float xt = __ldg(ri + t);
        const float xp = __ldg(ri + t + 1);
        const float yt = __ldg(ro + t);
        const float yp = __ldg(ro + t + 1);
        const float bR = (yp - yt) * (1.0f / (xp - xt));

        int s0 = (int)ceilf(__fmul_rn(__fsub_rn(xt, glo), invw));
        int s1 = (t + 1 < R - 1)
                   ? (int)ceilf(__fmul_rn(__fsub_rn(xp, glo), invw))
                   : (KBUCK + 1);
        s0 = max(s0, 0);
        s1 = min(s1, KBUCK + 1);
        for (int e = s0; e < s1; ++e) {
            float ex = fmaf((float)e, w, glo);
            edge[e] = fmaf(bR, ex - xt, yt);
        }
    }
    __syncthreads();

    // ---- pass 2: chord slope/intercept per bucket (absolute x coords) ----
    for (int b = threadIdx.x; b < KBUCK; b += THREADS) {
        float yl = edge[b];
        float yh = edge[b + 1];
        float xb = fmaf((float)b, w, glo);
        float s  = (yh - yl) * invw;       // (yh-yl)/w
        tab[b] = make_float2(s, fmaf(-s, xb, yl));
    }
    __syncthreads();

    const float roLo = __ldg(&ro[0]);
    const float roHi = __ldg(&ro[R - 1]);

    auto fast = [&](float xv, bool& oob) -> float {
        float fb = fmaf(xv, invw, nglo);
        int b = __float2int_rd(fb);                       // floor
        oob = ((unsigned)b >= (unsigned)KBUCK);
        b = min(max(b, 0), KBUCK - 1);
        float2 c = tab[b];                                // unconditional LDS.64
        return fmaf(c.x, xv, c.y);
    };

    auto fix = [&](float xv) -> float {                   // rare exact path
        if (xv >= hi) return roHi;
        if (xv <= lo) return roLo;
        return slow_eval(xv, (xv < glo) ? 1 : (R - 1), ri, ro, R);
    };

    // ---- streaming phase ----
    const int n4 = n >> 2;
    const float4* __restrict__ x4 = (const float4*)x;
    float4* __restrict__ o4 = (float4*)out;

    for (int i = blockIdx.x * THREADS + threadIdx.x; i < n4; i += GRID * THREADS) {
        float4 v = x4[i];
        bool b0, b1, b2, b3;
        float4 o;
        o.x = fast(v.x, b0);
        o.y = fast(v.y, b1);
        o.z = fast(v.z, b2);
        o.w = fast(v.w, b3);
        if (b0 | b1 | b2 | b3) {                          // ~0.2% of warp-iters
            if (b0) o.x = fix(v.x);
            if (b1) o.y = fix(v.y);
            if (b2) o.z = fix(v.z);
            if (b3) o.w = fix(v.w);
        }
        o4[i] = o;
    }

    const int base = n4 << 2;   // tail (n % 4)
    if (blockIdx.x == 0) {
        for (int i = base + threadIdx.x; i < n; i += THREADS) {
            bool ob;
            float y = fast(x[i], ob);
            out[i] = ob ? fix(x[i]) : y;
        }
    }
}

extern "C" void kernel_launch(void* const* d_in, const int* in_sizes, int n_in,
                              void* d_out, int out_size) {
    const float* x  = (const float*)d_in[0];
    const float* ri = (const float*)d_in[1];
    const float* ro = (const float*)d_in[2];
    float* out      = (float*)d_out;
    const int n = in_sizes[0];
    const int R = in_sizes[1];
    cudaFuncSetAttribute(calib_kernel, cudaFuncAttributeMaxDynamicSharedMemorySize,
                         SMEM_BYTES);
    calib_kernel<<<GRID, THREADS, SMEM_BYTES>>>(x, ri, ro, out, n, R);
}

// round 7
// speedup vs baseline: 1.0864x; 1.0864x over previous
#include <cuda_runtime.h>

// CalibrationLayer R7: slope/intercept chord table, IN-PLACE build (no scratch).
//
// Eval (minimal): b = floor(fma(xv, invw, nglo)); y = fma(tab[b].x, xv, tab[b].y)
// Build: pass 1 scatters the K+1 exact edge values into the table's .x slots
// (smem[2e]); pass 2 converts in place to {slope, intercept} with a chunked
// read/sync/write sweep. Footprint = KBUCK*8 + 16 = 114.7KB/CTA ->
// 2 CTAs x 1024 thr/SM (full occupancy) — fixing R6's 172KB/CTA occupancy bug.
// Out-of-grid tail (5.6e-4 of mass) + exact end clamps via rare fixup branch.

#define THREADS 1024
#define CTAS_PER_SM 2
#define GRID    (148 * CTAS_PER_SM)
#define KBUCK   14336
#define SMEM_BYTES (KBUCK * 8 + 16)   // table + one spare edge slot
#define GRANGE  3.45f

extern __shared__ float smem[];   // interleaved: edge[e] at smem[2e] during build

__device__ __forceinline__ float slow_eval(float xv, int start,
                                           const float* __restrict__ ri,
                                           const float* __restrict__ ro,
                                           int R) {
    int j = min(max(start, 1), R - 1);
    while (__ldg(ri + j) <= xv) ++j;       // exact upper_bound
    while (__ldg(ri + j - 1) > xv) --j;
    float x0 = __ldg(ri + j - 1), x1 = __ldg(ri + j);
    float y0 = __ldg(ro + j - 1), y1 = __ldg(ro + j);
    return y0 + (y1 - y0) * __fdividef(xv - x0, x1 - x0);
}

__global__ __launch_bounds__(THREADS, CTAS_PER_SM)
void calib_kernel(const float* __restrict__ x,
                  const float* __restrict__ ri,
                  const float* __restrict__ ro,
                  float* __restrict__ out,
                  int n, int R) {
    float2* __restrict__ tab = (float2*)smem;

    const float lo = __ldg(&ri[0]);
    const float hi = __ldg(&ri[R - 1]);
    float glo = fmaxf(lo, -GRANGE);
    float ghi = fminf(hi,  GRANGE);
    if (!(ghi - glo > 1e-6f)) { glo = lo; ghi = hi; }
    const float w    = (ghi - glo) / (float)KBUCK;
    const float invw = (float)KBUCK / (ghi - glo);
    const float nglo = -glo * invw;        // fb = fma(xv, invw, nglo)

    // ---- pass 1: exact interpolant values at the K+1 edges -> smem[2e] ----
    // Edge e lies in exactly one interval (identical fp range expressions),
    // so every slot 0..KBUCK is written exactly once.
    for (int t = threadIdx.x; t < R - 1; t += THREADS) {
        const float xt = __ldg(ri + t);
        const float xp = __ldg(ri + t + 1);
        const float yt = __ldg(ro + t);
        const float yp = __ldg(ro + t + 1);
        const float bR = (yp - yt) * (1.0f / (xp - xt));

        int s0 = (int)ceilf(__fmul_rn(__fsub_rn(xt, glo), invw));
        int s1 = (t + 1 < R - 1)
                   ? (int)ceilf(__fmul_rn(__fsub_rn(xp, glo), invw))
                   : (KBUCK + 1);
        s0 = max(s0, 0);
        s1 = min(s1, KBUCK + 1);
        for (int e = s0; e < s1; ++e) {
            float ex = fmaf((float)e, w, glo);
            smem[2 * e] = fmaf(bR, ex - xt, yt);
        }
    }
    __syncthreads();

    // ---- pass 2: in-place convert to {slope, intercept} ----
    // Chunked: read both edges, sync, write record. Cross-chunk read-ahead is
    // safe (later chunks' writes happen after this chunk's reads).
    for (int base = 0; base < KBUCK; base += THREADS) {
        int b = base + (int)threadIdx.x;
        bool valid = (b < KBUCK);
        float yl = 0.f, yh = 0.f, xb = 0.f;
        if (valid) {
            yl = smem[2 * b];
            yh = smem[2 * b + 2];
            xb = fmaf((float)b, w, glo);
        }
        __syncthreads();
        if (valid) {
            float s = (yh - yl) * invw;    // (yh - yl) / w
            tab[b] = make_float2(s, fmaf(-s, xb, yl));
        }
        __syncthreads();
    }

    const float roLo = __ldg(&ro[0]);
    const float roHi = __ldg(&ro[R - 1]);

    auto fast = [&](float xv, bool& oob) -> float {
        float fb = fmaf(xv, invw, nglo);
        int b = __float2int_rd(fb);                       // floor
        oob = ((unsigned)b >= (unsigned)KBUCK);
        b = min(max(b, 0), KBUCK - 1);
        float2 c = tab[b];                                // unconditional LDS.64
        return fmaf(c.x, xv, c.y);
    };

    auto fix = [&](float xv) -> float {                   // rare exact path
        if (xv >= hi) return roHi;
        if (xv <= lo) return roLo;
        return slow_eval(xv, (xv < glo) ? 1 : (R - 1), ri, ro, R);
    };

    // ---- streaming phase ----
    const int n4 = n >> 2;
    const float4* __restrict__ x4 = (const float4*)x;
    float4* __restrict__ o4 = (float4*)out;

    for (int i = blockIdx.x * THREADS + threadIdx.x; i < n4; i += GRID * THREADS) {
        float4 v = x4[i];
        bool b0, b1, b2, b3;
        float4 o;
        o.x = fast(v.x, b0);
        o.y = fast(v.y, b1);
        o.z = fast(v.z, b2);
        o.w = fast(v.w, b3);
        if (b0 | b1 | b2 | b3) {                          // ~0.2% of warp-iters
            if (b0) o.x = fix(v.x);
            if (b1) o.y = fix(v.y);
            if (b2) o.z = fix(v.z);
            if (b3) o.w = fix(v.w);
        }
        o4[i] = o;
    }

    const int base = n4 << 2;   // tail (n % 4)
    if (blockIdx.x == 0) {
        for (int i = base + threadIdx.x; i < n; i += THREADS) {
            bool ob;
            float y = fast(x[i], ob);
            out[i] = ob ? fix(x[i]) : y;
        }
    }
}

extern "C" void kernel_launch(void* const* d_in, const int* in_sizes, int n_in,
                              void* d_out, int out_size) {
    const float* x  = (const float*)d_in[0];
    const float* ri = (const float*)d_in[1];
    const float* ro = (const float*)d_in[2];
    float* out      = (float*)d_out;
    const int n = in_sizes[0];
    const int R = in_sizes[1];
    cudaFuncSetAttribute(calib_kernel, cudaFuncAttributeMaxDynamicSharedMemorySize,
                         SMEM_BYTES);
    calib_kernel<<<GRID, THREADS, SMEM_BYTES>>>(x, ri, ro, out, n, R);
}